// round 12
// baseline (speedup 1.0000x reference)
#include <cuda_runtime.h>
#include <cuda_fp16.h>
#include <cstdint>

#define BB 4
#define TT 32
#define SS 1024
#define HH 512
#define H2 1024
#define H3 1536

typedef unsigned long long ull;

// ---------------------------------------------------------------------------
// Scratch (allocation-free: __device__ globals)
// ---------------------------------------------------------------------------
__device__ float g_qf[BB * TT * H2];          // 512 KB
__device__ float g_sf[(size_t)BB * SS * H2];  // 16 MB
__device__ float g_attn[BB * TT * SS];        // 512 KB
// fp16 operands, row-major K-major:
__device__ __align__(16) char gA_hi[8 << 20];  // states fp16 [4096][1024]
__device__ __align__(16) char gB_hi[2 << 20];  // Ws^T hi [1024][1024]
__device__ __align__(16) char gB_lo[2 << 20];  // Ws^T lo

__device__ __forceinline__ uint32_t smem_u32(const void* p) {
    uint32_t a;
    asm("{ .reg .u64 t; cvta.to.shared.u64 t, %1; cvt.u32.u64 %0, t; }" : "=r"(a) : "l"(p));
    return a;
}

__device__ __forceinline__ uint32_t pack2h(float a, float b) {
    __half2 h = __floats2half2_rn(a, b);
    return *(uint32_t*)&h;
}

__device__ __forceinline__ uint32_t f16x2_pack(float lo, float hi) {
    uint32_t r;
    asm("cvt.rn.f16x2.f32 %0, %1, %2;" : "=r"(r) : "f"(hi), "f"(lo));
    return r;
}
__device__ __forceinline__ uint32_t tanh_h2(uint32_t x) {
    uint32_t y;
    asm("tanh.approx.f16x2 %0, %1;" : "=r"(y) : "r"(x));
    return y;
}
__device__ __forceinline__ float2 f16x2_unpack(uint32_t p) {
    float lo, hi;
    asm("{ .reg .b16 l, h; mov.b32 {l, h}, %2; cvt.f32.f16 %0, l; cvt.f32.f16 %1, h; }"
        : "=f"(lo), "=f"(hi) : "r"(p));
    return make_float2(lo, hi);
}

// ---- baseline-PTX tensor ops (sm_80+) -------------------------------------
#define LDSM_X4(r, a) \
    asm volatile("ldmatrix.sync.aligned.m8n8.x4.shared.b16 {%0,%1,%2,%3}, [%4];" \
                 : "=r"((r)[0]), "=r"((r)[1]), "=r"((r)[2]), "=r"((r)[3]) : "r"(a))

__device__ __forceinline__ void hmma(float* c, const uint32_t* a, uint32_t b0, uint32_t b1) {
    asm volatile(
        "mma.sync.aligned.m16n8k16.row.col.f32.f16.f16.f32 "
        "{%0,%1,%2,%3}, {%4,%5,%6,%7}, {%8,%9}, {%0,%1,%2,%3};"
        : "+f"(c[0]), "+f"(c[1]), "+f"(c[2]), "+f"(c[3])
        : "r"(a[0]), "r"(a[1]), "r"(a[2]), "r"(a[3]), "r"(b0), "r"(b1));
}

#define CP16(s, g) \
    asm volatile("cp.async.cg.shared.global [%0], [%1], 16;" :: "r"(s), "l"(g))
#define CPCOMMIT() asm volatile("cp.async.commit_group;" ::: "memory")
#define CPWAIT1() asm volatile("cp.async.wait_group 1;" ::: "memory")
#define CPWAIT0() asm volatile("cp.async.wait_group 0;" ::: "memory")

// ---------------------------------------------------------------------------
// pre_kernel: fused prelude. Block-range dispatch (long tasks first):
//  [0,64)      qf        = query @ Wq + bq -> g_qf
//  [64,128)    hid_q     = query @ Wc[1024:] + bc -> out_hid (direct store)
//  [128,384)   prep_B    = Ws -> gB_hi/gB_lo (transposed fp16 split)
//  [384,1408)  prep_A    = states -> gA_hi (fp16)
//  [1408,1440) zero      = out_ctx region
// 256 threads. All parts mutually independent.
// ---------------------------------------------------------------------------
__global__ __launch_bounds__(256) void pre_kernel(const float* __restrict__ query,
                                                  const float* __restrict__ Wq,
                                                  const float* __restrict__ bq,
                                                  const float* __restrict__ states,
                                                  const float* __restrict__ Ws,
                                                  const float* __restrict__ Wc,
                                                  const float* __restrict__ bc,
                                                  float* __restrict__ out_ctx,
                                                  float* __restrict__ out_hid) {
    __shared__ __align__(16) char shbuf[20736];
    int bid = blockIdx.x;
    int tid = threadIdx.x;

    if (bid < 64) {
        // ---- qf: jc 4 x tg 4 x b 4 ----
        float(*q_s)[HH] = (float(*)[HH])shbuf;  // 16 KB
        int jc = bid & 3, tg = (bid >> 2) & 3, b = bid >> 4;
        int j = jc * 256 + tid;
        int t0 = tg * 8;
        for (int i = tid; i < 8 * HH; i += 256) {
            int r = i >> 9, c = i & (HH - 1);
            q_s[r][c] = query[(size_t)(b * TT + t0 + r) * HH + c];
        }
        __syncthreads();
        float acc[8];
        float bias = bq[j];
#pragma unroll
        for (int i = 0; i < 8; i++) acc[i] = bias;
#pragma unroll 8
        for (int k = 0; k < HH; k++) {
            float w = Wq[(size_t)k * H2 + j];
#pragma unroll
            for (int i = 0; i < 8; i++) acc[i] = fmaf(q_s[i][k], w, acc[i]);
        }
#pragma unroll
        for (int i = 0; i < 8; i++)
            g_qf[(size_t)(b * TT + t0 + i) * H2 + j] = acc[i];
    } else if (bid < 128) {
        // ---- hid_q: hc 4 x tg 4 x b 4; K=512 split across 2 thread-halves,
        //      smem reduce, direct store (no atomics, no zero needed). ----
        int local = bid - 64;
        int hc = local & 3, tg = (local >> 2) & 3, b = local >> 4;
        int hl = tid & 127, kh = tid >> 7;  // kh in {0,1}
        int h = hc * 128 + hl;
        int t0 = tg * 8;
        float(*q_s)[HH] = (float(*)[HH])shbuf;       // 16 KB: 8 x 512
        float* red = (float*)(shbuf + 16384);        // 4 KB: 8 x 128
        for (int i = tid; i < 8 * HH; i += 256) {
            int r = i >> 9, c = i & (HH - 1);
            q_s[r][c] = query[(size_t)(b * TT + t0 + r) * HH + c];
        }
        __syncthreads();
        float acc[8] = {};
        int kbase = kh * 256;
#pragma unroll 4
        for (int k = 0; k < 256; k++) {
            float w = Wc[(size_t)(H2 + kbase + k) * HH + h];
#pragma unroll
            for (int i = 0; i < 8; i++) acc[i] = fmaf(q_s[i][kbase + k], w, acc[i]);
        }
        __syncthreads();  // q_s reads done before red overlaps? red is separate region; sync for store order
        if (kh == 1) {
#pragma unroll
            for (int i = 0; i < 8; i++) red[i * 128 + hl] = acc[i];
        }
        __syncthreads();
        if (kh == 0) {
            float bias = bc[h];
#pragma unroll
            for (int i = 0; i < 8; i++)
                out_hid[(size_t)(b * TT + t0 + i) * HH + h] =
                    bias + acc[i] + red[i * 128 + hl];
        }
    } else if (bid < 384) {
        // ---- prep_B: kt 16 x nb 16 ----
        int local = bid - 128;
        int k0 = (local & 15) * 64, n0 = (local >> 4) * 64;
        float(*tr)[65] = (float(*)[65])shbuf;  // 16.6 KB
        int ki = tid >> 2, nq = (tid & 3) * 16;
#pragma unroll
        for (int j = 0; j < 4; j++) {
            float4 vv = *(const float4*)(Ws + (size_t)(k0 + ki) * H2 + n0 + nq + j * 4);
            tr[nq + j * 4 + 0][ki] = vv.x;
            tr[nq + j * 4 + 1][ki] = vv.y;
            tr[nq + j * 4 + 2][ki] = vv.z;
            tr[nq + j * 4 + 3][ki] = vv.w;
        }
        __syncthreads();
        int nr_l = tid >> 2, kq = (tid & 3) * 16;
        int n_g = n0 + nr_l;
#pragma unroll
        for (int j = 0; j < 4; j++) {
            int kr = kq + j * 4;
            float x0 = tr[nr_l][kr], x1 = tr[nr_l][kr + 1];
            float x2 = tr[nr_l][kr + 2], x3 = tr[nr_l][kr + 3];
            float h0 = __half2float(__float2half_rn(x0));
            float h1 = __half2float(__float2half_rn(x1));
            float h2 = __half2float(__float2half_rn(x2));
            float h3 = __half2float(__float2half_rn(x3));
            ull hi = (ull)pack2h(h0, h1) | ((ull)pack2h(h2, h3) << 32);
            ull lo = (ull)pack2h(x0 - h0, x1 - h1) |
                     ((ull)pack2h(x2 - h2, x3 - h3) << 32);
            size_t off = ((size_t)n_g * H2 + k0 + kr) * 2;
            *(ull*)(gB_hi + off) = hi;
            *(ull*)(gB_lo + off) = lo;
        }
    } else if (bid < 1408) {
        // ---- prep_A ----
        int idx = (bid - 384) * 256 + tid;
#pragma unroll
        for (int q = 0; q < 4; q++) {
            int fid = idx * 4 + q;
            float4 vvv = *(const float4*)(states + (size_t)fid * 4);
            ull hi = (ull)pack2h(vvv.x, vvv.y) | ((ull)pack2h(vvv.z, vvv.w) << 32);
            *(ull*)(gA_hi + (size_t)fid * 8) = hi;
        }
    } else {
        // ---- zero out_ctx (32768 float4) ----
        int i = (bid - 1408) * 1024 + tid;
        float4* p = (float4*)out_ctx;
#pragma unroll
        for (int u = 0; u < 4; u++) p[i + u * 256] = make_float4(0.f, 0.f, 0.f, 0.f);
    }
}

// ---------------------------------------------------------------------------
// K2: sf = states @ Ws via mma.sync fp16 2-MMA split (Ah*Bh + Ah*Bl).
// Block tile 256x64, 512 thr, warp tile 64x16, grid 16x16 = 256 blocks.
// ---------------------------------------------------------------------------
#define ROWB 144
#define A_TILE (256 * ROWB)
#define B_TILE (64 * ROWB)
#define STAGEB (A_TILE + 2 * B_TILE)
#define SMEM_MMA (2 * STAGEB)

__device__ __forceinline__ void load_chunk(uint32_t sst, const char* gAh,
                                           const char* gBh, const char* gBl,
                                           int c, int tid) {
#pragma unroll
    for (int r = 0; r < 4; r++) {
        int i = r * 512 + tid;
        int row = i >> 3, quad = i & 7;
        uint32_t soff = row * ROWB + quad * 16;
        size_t goff = (size_t)row * 2048 + (size_t)c * 128 + quad * 16;
        CP16(sst + soff, gAh + goff);
    }
    {
        int row = tid >> 3, quad = tid & 7;
        uint32_t soff = row * ROWB + quad * 16;
        size_t goff = (size_t)row * 2048 + (size_t)c * 128 + quad * 16;
        CP16(sst + A_TILE + soff, gBh + goff);
        CP16(sst + A_TILE + B_TILE + soff, gBl + goff);
    }
}

__global__ __launch_bounds__(512, 1) void sf_mma() {
    extern __shared__ __align__(16) char sm[];
    uint32_t sbase = smem_u32(sm);
    int tid = threadIdx.x, lane = tid & 31, warp = tid >> 5;
    int nt = blockIdx.x, mt = blockIdx.y;
    int wm = warp >> 2, wn = warp & 3;

    const char* gAh = gA_hi + (size_t)(mt * 256) * 2048;
    const char* gBh = gB_hi + (size_t)(nt * 64) * 2048;
    const char* gBl = gB_lo + (size_t)(nt * 64) * 2048;

    float cacc[4][2][4] = {};

    load_chunk(sbase, gAh, gBh, gBl, 0, tid);
    CPCOMMIT();

#pragma unroll 1
    for (int c = 0; c < 16; c++) {
        int cur = c & 1;
        if (c + 1 < 16) {
            load_chunk(sbase + (cur ^ 1) * STAGEB, gAh, gBh, gBl, c + 1, tid);
            CPCOMMIT();
            CPWAIT1();
        } else {
            CPWAIT0();
        }
        __syncthreads();

        uint32_t sA = sbase + cur * STAGEB;
        uint32_t sB_h = sA + A_TILE;
        uint32_t sB_l = sB_h + B_TILE;
        int r16 = lane & 15, hx = lane >> 4;

#pragma unroll
        for (int k16 = 0; k16 < 4; k16++) {
            int kb = k16 * 32 + hx * 16;
            uint32_t ah[4][4];
#pragma unroll
            for (int mf = 0; mf < 4; mf++)
                LDSM_X4(ah[mf], sA + (wm * 64 + mf * 16 + r16) * ROWB + kb);
            {
                uint32_t bh[4];
                LDSM_X4(bh, sB_h + (wn * 16 + r16) * ROWB + kb);
#pragma unroll
                for (int mf = 0; mf < 4; mf++)
#pragma unroll
                    for (int nf = 0; nf < 2; nf++)
                        hmma(cacc[mf][nf], ah[mf], bh[nf], bh[nf + 2]);
            }
            {
                uint32_t bl[4];
                LDSM_X4(bl, sB_l + (wn * 16 + r16) * ROWB + kb);
#pragma unroll
                for (int mf = 0; mf < 4; mf++)
#pragma unroll
                    for (int nf = 0; nf < 2; nf++)
                        hmma(cacc[mf][nf], ah[mf], bl[nf], bl[nf + 2]);
            }
        }
        __syncthreads();
    }

    int tg = lane >> 2, tq = lane & 3;
#pragma unroll
    for (int mf = 0; mf < 4; mf++) {
#pragma unroll
        for (int nf = 0; nf < 2; nf++) {
            float* base = g_sf + (size_t)(mt * 256 + wm * 64 + mf * 16 + tg) * H2 +
                          nt * 64 + wn * 16 + nf * 8 + tq * 2;
            float2 v0 = {cacc[mf][nf][0], cacc[mf][nf][1]};
            float2 v1 = {cacc[mf][nf][2], cacc[mf][nf][3]};
            *(float2*)base = v0;
            *(float2*)(base + 8 * H2) = v1;
        }
    }
}

// ---------------------------------------------------------------------------
// K3a: raw alignments, f16x2 tanh. Block (sc, b), 512 thr, qf[b] in smem;
// 2 s-rows/warp preloaded in regs.
// ---------------------------------------------------------------------------
__global__ __launch_bounds__(512, 1) void align_kernel(const float* __restrict__ v) {
    extern __shared__ float qf_s[];  // [TT][H2] = 128 KB
    int sc = blockIdx.x, b = blockIdx.y;
    int tid = threadIdx.x, lane = tid & 31, warp = tid >> 5;

    const float4* qsrc = (const float4*)(g_qf + (size_t)b * TT * H2);
    float4* qdst = (float4*)qf_s;
#pragma unroll
    for (int i = 0; i < 16; i++) qdst[tid + i * 512] = qsrc[tid + i * 512];

    int s0 = sc * 32 + warp * 2;
    float4 sv[2][8];
#pragma unroll
    for (int si = 0; si < 2; si++) {
        const float* sfrow = g_sf + ((size_t)(b * SS + s0 + si)) * H2;
#pragma unroll
        for (int u = 0; u < 8; u++)
            sv[si][u] = *(const float4*)(sfrow + u * 128 + lane * 4);
    }
    __syncthreads();

    float* ga = g_attn + (size_t)(b * TT) * SS + s0;
#pragma unroll 1
    for (int t = 0; t < TT; t++) {
        const float* qrow = qf_s + t * H2;
        float a00 = 0.f, a01 = 0.f, a10 = 0.f, a11 = 0.f;
#pragma unroll
        for (int u = 0; u < 8; u++) {
            float4 q = *(const float4*)(qrow + u * 128 + lane * 4);
            float4 vv = __ldg((const float4*)(v + u * 128 + lane * 4));
            uint32_t p0 = tanh_h2(f16x2_pack(q.x + sv[0][u].x, q.y + sv[0][u].y));
            uint32_t p1 = tanh_h2(f16x2_pack(q.z + sv[0][u].z, q.w + sv[0][u].w));
            uint32_t p2 = tanh_h2(f16x2_pack(q.x + sv[1][u].x, q.y + sv[1][u].y));
            uint32_t p3 = tanh_h2(f16x2_pack(q.z + sv[1][u].z, q.w + sv[1][u].w));
            float2 t0 = f16x2_unpack(p0), t1 = f16x2_unpack(p1);
            float2 t2 = f16x2_unpack(p2), t3 = f16x2_unpack(p3);
            a00 = fmaf(t0.x, vv.x, a00);
            a01 = fmaf(t0.y, vv.y, a01);
            a00 = fmaf(t1.x, vv.z, a00);
            a01 = fmaf(t1.y, vv.w, a01);
            a10 = fmaf(t2.x, vv.x, a10);
            a11 = fmaf(t2.y, vv.y, a11);
            a10 = fmaf(t3.x, vv.z, a10);
            a11 = fmaf(t3.y, vv.w, a11);
        }
        float acc0 = a00 + a01;
        float acc1 = a10 + a11;
#pragma unroll
        for (int o = 16; o; o >>= 1) {
            acc0 += __shfl_xor_sync(0xffffffffu, acc0, o);
            acc1 += __shfl_xor_sync(0xffffffffu, acc1, o);
        }
        if (lane == 0) {
            ga[(size_t)t * SS] = acc0;
            ga[(size_t)t * SS + 1] = acc1;
        }
    }
}

// ---------------------------------------------------------------------------
// K3b: mask + softmax.
// ---------------------------------------------------------------------------
__global__ __launch_bounds__(256) void softmax_kernel(const int* __restrict__ mask,
                                                      float* __restrict__ out_att) {
    int t = blockIdx.x, b = blockIdx.y;
    int tid = threadIdx.x, lane = tid & 31, warp = tid >> 5;
    __shared__ float red[8];

    float* ga = g_attn + (size_t)(b * TT + t) * SS;
    float al[4];
#pragma unroll
    for (int i = 0; i < 4; i++) {
        int s = tid + i * 256;
        al[i] = mask[b * SS + s] ? ga[s] : -1e30f;
    }

    float m = fmaxf(fmaxf(al[0], al[1]), fmaxf(al[2], al[3]));
#pragma unroll
    for (int o = 16; o; o >>= 1) m = fmaxf(m, __shfl_xor_sync(0xffffffffu, m, o));
    if (lane == 0) red[warp] = m;
    __syncthreads();
    float mx = -1e30f;
#pragma unroll
    for (int i = 0; i < 8; i++) mx = fmaxf(mx, red[i]);

    float e[4];
    float ssum = 0.f;
#pragma unroll
    for (int i = 0; i < 4; i++) {
        e[i] = __expf(al[i] - mx);
        ssum += e[i];
    }
#pragma unroll
    for (int o = 16; o; o >>= 1) ssum += __shfl_xor_sync(0xffffffffu, ssum, o);
    __syncthreads();
    if (lane == 0) red[warp] = ssum;
    __syncthreads();
    float tot = 0.f;
#pragma unroll
    for (int i = 0; i < 8; i++) tot += red[i];
    float inv = 1.0f / tot;

    float* oa = out_att + (size_t)b * SS * TT + t;
#pragma unroll
    for (int i = 0; i < 4; i++) {
        int s = tid + i * 256;
        float w = e[i] * inv;
        ga[s] = w;
        oa[(size_t)s * TT] = w;
    }
}

// ---------------------------------------------------------------------------
// K4: context = attn @ states, split-S (32) with atomicAdd epilogue.
// ---------------------------------------------------------------------------
__global__ __launch_bounds__(128) void ctx_kernel(const float* __restrict__ states,
                                                  float* __restrict__ out_ctx) {
    int dc = blockIdx.x, sc = blockIdx.y, b = blockIdx.z;
    int d = dc * 128 + threadIdx.x;
    int s0 = sc * 32;
    __shared__ float aw[TT][32];
    for (int i = threadIdx.x; i < TT * 32; i += 128) {
        int t = i >> 5, sl = i & 31;
        aw[t][sl] = g_attn[(size_t)(b * TT + t) * SS + s0 + sl];
    }
    __syncthreads();
    float acc[TT] = {};
    const float* sb = states + ((size_t)b * SS + s0) * H2 + d;
#pragma unroll 4
    for (int sl = 0; sl < 32; sl++) {
        float sv = sb[(size_t)sl * H2];
#pragma unroll
        for (int t = 0; t < TT; t++) acc[t] = fmaf(aw[t][sl], sv, acc[t]);
    }
#pragma unroll
    for (int t = 0; t < TT; t++)
        atomicAdd(&out_ctx[(size_t)(b * TT + t) * H2 + d], acc[t]);
}

// ---------------------------------------------------------------------------
// K5: attention_hidden += context @ Wc[0:1024]. Split-K atomics (base value
// incl. bias + query part was stored by pre_kernel's hid_q branch).
// ---------------------------------------------------------------------------
__global__ __launch_bounds__(128) void hidden_kernel(const float* __restrict__ Wc,
                                                     const float* __restrict__ ctx,
                                                     float* __restrict__ out_hid) {
    int hc = blockIdx.x, tg = blockIdx.y;
    int b = blockIdx.z >> 4, kc = blockIdx.z & 15;
    int h = hc * 128 + threadIdx.x;
    int t0 = tg * 8, k0 = kc * 64;
    __shared__ float cc[8][64];
    for (int i = threadIdx.x; i < 8 * 64; i += 128) {
        int r = i >> 6, col = i & 63;
        cc[r][col] = ctx[(size_t)(b * TT + t0 + r) * H2 + k0 + col];
    }
    __syncthreads();
    float acc[8] = {};
#pragma unroll 4
    for (int k = 0; k < 64; k++) {
        float w = Wc[(size_t)(k0 + k) * HH + h];
#pragma unroll
        for (int i = 0; i < 8; i++) acc[i] = fmaf(cc[i][k], w, acc[i]);
    }
#pragma unroll
    for (int i = 0; i < 8; i++)
        atomicAdd(&out_hid[(size_t)(b * TT + t0 + i) * HH + h], acc[i]);
}

// ---------------------------------------------------------------------------
extern "C" void kernel_launch(void* const* d_in, const int* in_sizes, int n_in,
                              void* d_out, int out_size) {
    const float* query  = (const float*)d_in[0];
    const float* states = (const float*)d_in[1];
    const int*   mask   = (const int*)d_in[2];
    const float* Wq     = (const float*)d_in[3];
    const float* bq     = (const float*)d_in[4];
    const float* Ws     = (const float*)d_in[5];
    const float* v      = (const float*)d_in[6];
    const float* Wc     = (const float*)d_in[7];
    const float* bc     = (const float*)d_in[8];

    float* out_ctx = (float*)d_out;                  // (B,T,2H)
    float* out_hid = out_ctx + BB * TT * H2;         // (B,T,H)
    float* out_att = out_hid + BB * TT * HH;         // (B,S,T)

    static int attr_set = 0;
    if (!attr_set) {
        cudaFuncSetAttribute(align_kernel,
                             cudaFuncAttributeMaxDynamicSharedMemorySize,
                             TT * H2 * sizeof(float));
        cudaFuncSetAttribute(sf_mma,
                             cudaFuncAttributeMaxDynamicSharedMemorySize,
                             SMEM_MMA);
        attr_set = 1;
    }

    pre_kernel<<<1440, 256>>>(query, Wq, bq, states, Ws, Wc, bc, out_ctx, out_hid);
    sf_mma<<<dim3(16, 16), 512, SMEM_MMA>>>();
    align_kernel<<<dim3(32, BB), 512, TT * H2 * sizeof(float)>>>(v);
    softmax_kernel<<<dim3(TT, BB), 256>>>(mask, out_att);
    ctx_kernel<<<dim3(8, 32, 4), 128>>>(states, out_ctx);
    hidden_kernel<<<dim3(4, 4, 64), 128>>>(Wc, out_ctx, out_hid);
}

// round 13
// speedup vs baseline: 1.1260x; 1.1260x over previous
#include <cuda_runtime.h>
#include <cuda_fp16.h>
#include <cstdint>

#define BB 4
#define TT 32
#define SS 1024
#define HH 512
#define H2 1024
#define H3 1536

typedef unsigned long long ull;

// ---------------------------------------------------------------------------
// Scratch (allocation-free: __device__ globals)
// ---------------------------------------------------------------------------
__device__ float g_qf[BB * TT * H2];          // 512 KB
__device__ float g_sf[(size_t)BB * SS * H2];  // 16 MB
__device__ float g_attn[BB * TT * SS];        // 512 KB (masked raw scores)
__device__ float2 g_pstat[BB][32][TT];        // per-slice softmax stats (m, sumexp)
// fp16 operands, row-major K-major:
__device__ __align__(16) char gA_hi[8 << 20];  // states fp16 [4096][1024]
__device__ __align__(16) char gB_hi[2 << 20];  // Ws^T hi [1024][1024]
__device__ __align__(16) char gB_lo[2 << 20];  // Ws^T lo

__device__ __forceinline__ uint32_t smem_u32(const void* p) {
    uint32_t a;
    asm("{ .reg .u64 t; cvta.to.shared.u64 t, %1; cvt.u32.u64 %0, t; }" : "=r"(a) : "l"(p));
    return a;
}

__device__ __forceinline__ uint32_t pack2h(float a, float b) {
    __half2 h = __floats2half2_rn(a, b);
    return *(uint32_t*)&h;
}

__device__ __forceinline__ uint32_t f16x2_pack(float lo, float hi) {
    uint32_t r;
    asm("cvt.rn.f16x2.f32 %0, %1, %2;" : "=r"(r) : "f"(hi), "f"(lo));
    return r;
}
__device__ __forceinline__ uint32_t tanh_h2(uint32_t x) {
    uint32_t y;
    asm("tanh.approx.f16x2 %0, %1;" : "=r"(y) : "r"(x));
    return y;
}
__device__ __forceinline__ float2 f16x2_unpack(uint32_t p) {
    float lo, hi;
    asm("{ .reg .b16 l, h; mov.b32 {l, h}, %2; cvt.f32.f16 %0, l; cvt.f32.f16 %1, h; }"
        : "=f"(lo), "=f"(hi) : "r"(p));
    return make_float2(lo, hi);
}

// ---- baseline-PTX tensor ops (sm_80+) -------------------------------------
#define LDSM_X4(r, a) \
    asm volatile("ldmatrix.sync.aligned.m8n8.x4.shared.b16 {%0,%1,%2,%3}, [%4];" \
                 : "=r"((r)[0]), "=r"((r)[1]), "=r"((r)[2]), "=r"((r)[3]) : "r"(a))

__device__ __forceinline__ void hmma(float* c, const uint32_t* a, uint32_t b0, uint32_t b1) {
    asm volatile(
        "mma.sync.aligned.m16n8k16.row.col.f32.f16.f16.f32 "
        "{%0,%1,%2,%3}, {%4,%5,%6,%7}, {%8,%9}, {%0,%1,%2,%3};"
        : "+f"(c[0]), "+f"(c[1]), "+f"(c[2]), "+f"(c[3])
        : "r"(a[0]), "r"(a[1]), "r"(a[2]), "r"(a[3]), "r"(b0), "r"(b1));
}

#define CP16(s, g) \
    asm volatile("cp.async.cg.shared.global [%0], [%1], 16;" :: "r"(s), "l"(g))
#define CPCOMMIT() asm volatile("cp.async.commit_group;" ::: "memory")
#define CPWAIT1() asm volatile("cp.async.wait_group 1;" ::: "memory")
#define CPWAIT0() asm volatile("cp.async.wait_group 0;" ::: "memory")

// ---------------------------------------------------------------------------
// K0: zero out_ctx + out_hid (atomicAdd targets). 196608 floats = 49152 f4.
// ---------------------------------------------------------------------------
__global__ __launch_bounds__(256) void zero_kernel(float4* __restrict__ p) {
    int i = blockIdx.x * 1024 + threadIdx.x;
#pragma unroll
    for (int u = 0; u < 4; u++) p[i + u * 256] = make_float4(0.f, 0.f, 0.f, 0.f);
}

// ---------------------------------------------------------------------------
// K1: qf = query @ Wq + bq   (128 x 1024, K=512)
// ---------------------------------------------------------------------------
__global__ __launch_bounds__(128) void qf_kernel(const float* __restrict__ query,
                                                 const float* __restrict__ Wq,
                                                 const float* __restrict__ bq) {
    int jc = blockIdx.x, tg = blockIdx.y, b = blockIdx.z;
    int j = jc * 128 + threadIdx.x;
    int t0 = tg * 8;
    __shared__ float q_s[8][HH];
    for (int i = threadIdx.x; i < 8 * HH; i += 128) {
        int r = i >> 9, c = i & (HH - 1);
        q_s[r][c] = query[(size_t)(b * TT + t0 + r) * HH + c];
    }
    __syncthreads();
    float acc[8];
    float bias = bq[j];
#pragma unroll
    for (int i = 0; i < 8; i++) acc[i] = bias;
#pragma unroll 8
    for (int k = 0; k < HH; k++) {
        float w = Wq[(size_t)k * H2 + j];
#pragma unroll
        for (int i = 0; i < 8; i++) acc[i] = fmaf(q_s[i][k], w, acc[i]);
    }
#pragma unroll
    for (int i = 0; i < 8; i++)
        g_qf[(size_t)(b * TT + t0 + i) * H2 + j] = acc[i];
}

// ---------------------------------------------------------------------------
// K1b: out_hid += query @ Wc[1024:1536] (+bc at kc==0). Split-K atomics.
// grid (hc=4, tg=4, b*8+kc=32) = 512 blocks, 128 thr, K-chunk 64.
// ---------------------------------------------------------------------------
__global__ __launch_bounds__(128) void hid_q_kernel(const float* __restrict__ query,
                                                    const float* __restrict__ Wc,
                                                    const float* __restrict__ bc,
                                                    float* __restrict__ out_hid) {
    int hc = blockIdx.x, tg = blockIdx.y;
    int b = blockIdx.z >> 3, kc = blockIdx.z & 7;
    int h = hc * 128 + threadIdx.x;
    int t0 = tg * 8, k0 = kc * 64;
    __shared__ float q_s[8][64];
    for (int i = threadIdx.x; i < 8 * 64; i += 128) {
        int r = i >> 6, c = i & 63;
        q_s[r][c] = query[(size_t)(b * TT + t0 + r) * HH + k0 + c];
    }
    __syncthreads();
    float acc[8];
    float bias = (kc == 0) ? bc[h] : 0.f;
#pragma unroll
    for (int i = 0; i < 8; i++) acc[i] = bias;
#pragma unroll 4
    for (int k = 0; k < 64; k++) {
        float w = Wc[(size_t)(H2 + k0 + k) * HH + h];
#pragma unroll
        for (int i = 0; i < 8; i++) acc[i] = fmaf(q_s[i][k], w, acc[i]);
    }
#pragma unroll
    for (int i = 0; i < 8; i++)
        atomicAdd(&out_hid[(size_t)(b * TT + t0 + i) * HH + h], acc[i]);
}

// ---------------------------------------------------------------------------
// prep_A: states fp32 [4096,1024] -> gA_hi fp16 row-major (hi only).
// ---------------------------------------------------------------------------
__global__ __launch_bounds__(256) void prep_A(const float* __restrict__ A) {
    int idx = blockIdx.x * 256 + threadIdx.x;
#pragma unroll
    for (int q = 0; q < 4; q++) {
        int fid = idx * 4 + q;
        float4 vvv = *(const float4*)(A + (size_t)fid * 4);
        ull hi = (ull)pack2h(vvv.x, vvv.y) | ((ull)pack2h(vvv.z, vvv.w) << 32);
        *(ull*)(gA_hi + (size_t)fid * 8) = hi;
    }
}

// ---------------------------------------------------------------------------
// prep_B: Ws fp32 [K=1024, N=1024] -> gB_hi/gB_lo fp16 transposed [N][K].
// ---------------------------------------------------------------------------
__global__ __launch_bounds__(256) void prep_B(const float* __restrict__ W) {
    __shared__ float tr[64][65];
    int k0 = blockIdx.x * 64, n0 = blockIdx.y * 64;
    int tid = threadIdx.x;
    int ki = tid >> 2, nq = (tid & 3) * 16;
#pragma unroll
    for (int j = 0; j < 4; j++) {
        float4 vv = *(const float4*)(W + (size_t)(k0 + ki) * H2 + n0 + nq + j * 4);
        tr[nq + j * 4 + 0][ki] = vv.x;
        tr[nq + j * 4 + 1][ki] = vv.y;
        tr[nq + j * 4 + 2][ki] = vv.z;
        tr[nq + j * 4 + 3][ki] = vv.w;
    }
    __syncthreads();
    int nr_l = tid >> 2, kq = (tid & 3) * 16;
    int n_g = n0 + nr_l;
#pragma unroll
    for (int j = 0; j < 4; j++) {
        int kr = kq + j * 4;
        float x0 = tr[nr_l][kr], x1 = tr[nr_l][kr + 1];
        float x2 = tr[nr_l][kr + 2], x3 = tr[nr_l][kr + 3];
        float h0 = __half2float(__float2half_rn(x0));
        float h1 = __half2float(__float2half_rn(x1));
        float h2 = __half2float(__float2half_rn(x2));
        float h3 = __half2float(__float2half_rn(x3));
        ull hi = (ull)pack2h(h0, h1) | ((ull)pack2h(h2, h3) << 32);
        ull lo = (ull)pack2h(x0 - h0, x1 - h1) |
                 ((ull)pack2h(x2 - h2, x3 - h3) << 32);
        size_t off = ((size_t)n_g * H2 + k0 + kr) * 2;
        *(ull*)(gB_hi + off) = hi;
        *(ull*)(gB_lo + off) = lo;
    }
}

// ---------------------------------------------------------------------------
// K2: sf = states @ Ws via mma.sync fp16 2-MMA split (Ah*Bh + Ah*Bl).
// Block tile 256x64, 512 thr, warp tile 64x16, grid 16x16 = 256 blocks.
// ---------------------------------------------------------------------------
#define ROWB 144
#define A_TILE (256 * ROWB)
#define B_TILE (64 * ROWB)
#define STAGEB (A_TILE + 2 * B_TILE)
#define SMEM_MMA (2 * STAGEB)

__device__ __forceinline__ void load_chunk(uint32_t sst, const char* gAh,
                                           const char* gBh, const char* gBl,
                                           int c, int tid) {
#pragma unroll
    for (int r = 0; r < 4; r++) {
        int i = r * 512 + tid;
        int row = i >> 3, quad = i & 7;
        uint32_t soff = row * ROWB + quad * 16;
        size_t goff = (size_t)row * 2048 + (size_t)c * 128 + quad * 16;
        CP16(sst + soff, gAh + goff);
    }
    {
        int row = tid >> 3, quad = tid & 7;
        uint32_t soff = row * ROWB + quad * 16;
        size_t goff = (size_t)row * 2048 + (size_t)c * 128 + quad * 16;
        CP16(sst + A_TILE + soff, gBh + goff);
        CP16(sst + A_TILE + B_TILE + soff, gBl + goff);
    }
}

__global__ __launch_bounds__(512, 1) void sf_mma() {
    extern __shared__ __align__(16) char sm[];
    uint32_t sbase = smem_u32(sm);
    int tid = threadIdx.x, lane = tid & 31, warp = tid >> 5;
    int nt = blockIdx.x, mt = blockIdx.y;
    int wm = warp >> 2, wn = warp & 3;

    const char* gAh = gA_hi + (size_t)(mt * 256) * 2048;
    const char* gBh = gB_hi + (size_t)(nt * 64) * 2048;
    const char* gBl = gB_lo + (size_t)(nt * 64) * 2048;

    float cacc[4][2][4] = {};

    load_chunk(sbase, gAh, gBh, gBl, 0, tid);
    CPCOMMIT();

#pragma unroll 1
    for (int c = 0; c < 16; c++) {
        int cur = c & 1;
        if (c + 1 < 16) {
            load_chunk(sbase + (cur ^ 1) * STAGEB, gAh, gBh, gBl, c + 1, tid);
            CPCOMMIT();
            CPWAIT1();
        } else {
            CPWAIT0();
        }
        __syncthreads();

        uint32_t sA = sbase + cur * STAGEB;
        uint32_t sB_h = sA + A_TILE;
        uint32_t sB_l = sB_h + B_TILE;
        int r16 = lane & 15, hx = lane >> 4;

#pragma unroll
        for (int k16 = 0; k16 < 4; k16++) {
            int kb = k16 * 32 + hx * 16;
            uint32_t ah[4][4];
#pragma unroll
            for (int mf = 0; mf < 4; mf++)
                LDSM_X4(ah[mf], sA + (wm * 64 + mf * 16 + r16) * ROWB + kb);
            {
                uint32_t bh[4];
                LDSM_X4(bh, sB_h + (wn * 16 + r16) * ROWB + kb);
#pragma unroll
                for (int mf = 0; mf < 4; mf++)
#pragma unroll
                    for (int nf = 0; nf < 2; nf++)
                        hmma(cacc[mf][nf], ah[mf], bh[nf], bh[nf + 2]);
            }
            {
                uint32_t bl[4];
                LDSM_X4(bl, sB_l + (wn * 16 + r16) * ROWB + kb);
#pragma unroll
                for (int mf = 0; mf < 4; mf++)
#pragma unroll
                    for (int nf = 0; nf < 2; nf++)
                        hmma(cacc[mf][nf], ah[mf], bl[nf], bl[nf + 2]);
            }
        }
        __syncthreads();
    }

    int tg = lane >> 2, tq = lane & 3;
#pragma unroll
    for (int mf = 0; mf < 4; mf++) {
#pragma unroll
        for (int nf = 0; nf < 2; nf++) {
            float* base = g_sf + (size_t)(mt * 256 + wm * 64 + mf * 16 + tg) * H2 +
                          nt * 64 + wn * 16 + nf * 8 + tq * 2;
            float2 v0 = {cacc[mf][nf][0], cacc[mf][nf][1]};
            float2 v1 = {cacc[mf][nf][2], cacc[mf][nf][3]};
            *(float2*)base = v0;
            *(float2*)(base + 8 * H2) = v1;
        }
    }
}

// ---------------------------------------------------------------------------
// K3: alignments + mask + PER-SLICE softmax stats (flash two-level pass 1).
// Block (sc, b), 512 thr, qf[b] in dynamic smem; 2 s-rows/warp in regs.
// Writes masked raw scores to g_attn and (m, sumexp) per (b,sc,t) to g_pstat.
// ---------------------------------------------------------------------------
__global__ __launch_bounds__(512, 1) void align_kernel(const float* __restrict__ v,
                                                       const int* __restrict__ mask) {
    extern __shared__ float qf_s[];       // [TT][H2] = 128 KB dynamic
    __shared__ float scbuf[TT][32];       // 4 KB static: scores [t][s_local]
    int scb = blockIdx.x, b = blockIdx.y;
    int tid = threadIdx.x, lane = tid & 31, warp = tid >> 5;

    const float4* qsrc = (const float4*)(g_qf + (size_t)b * TT * H2);
    float4* qdst = (float4*)qf_s;
#pragma unroll
    for (int i = 0; i < 16; i++) qdst[tid + i * 512] = qsrc[tid + i * 512];

    int s0 = scb * 32 + warp * 2;
    int msk0 = mask[b * SS + s0];
    int msk1 = mask[b * SS + s0 + 1];
    float4 sv[2][8];
#pragma unroll
    for (int si = 0; si < 2; si++) {
        const float* sfrow = g_sf + ((size_t)(b * SS + s0 + si)) * H2;
#pragma unroll
        for (int u = 0; u < 8; u++)
            sv[si][u] = *(const float4*)(sfrow + u * 128 + lane * 4);
    }
    __syncthreads();

    float* ga = g_attn + (size_t)(b * TT) * SS + s0;
#pragma unroll 1
    for (int t = 0; t < TT; t++) {
        const float* qrow = qf_s + t * H2;
        float a00 = 0.f, a01 = 0.f, a10 = 0.f, a11 = 0.f;
#pragma unroll
        for (int u = 0; u < 8; u++) {
            float4 q = *(const float4*)(qrow + u * 128 + lane * 4);
            float4 vv = __ldg((const float4*)(v + u * 128 + lane * 4));
            uint32_t p0 = tanh_h2(f16x2_pack(q.x + sv[0][u].x, q.y + sv[0][u].y));
            uint32_t p1 = tanh_h2(f16x2_pack(q.z + sv[0][u].z, q.w + sv[0][u].w));
            uint32_t p2 = tanh_h2(f16x2_pack(q.x + sv[1][u].x, q.y + sv[1][u].y));
            uint32_t p3 = tanh_h2(f16x2_pack(q.z + sv[1][u].z, q.w + sv[1][u].w));
            float2 t0 = f16x2_unpack(p0), t1 = f16x2_unpack(p1);
            float2 t2 = f16x2_unpack(p2), t3 = f16x2_unpack(p3);
            a00 = fmaf(t0.x, vv.x, a00);
            a01 = fmaf(t0.y, vv.y, a01);
            a00 = fmaf(t1.x, vv.z, a00);
            a01 = fmaf(t1.y, vv.w, a01);
            a10 = fmaf(t2.x, vv.x, a10);
            a11 = fmaf(t2.y, vv.y, a11);
            a10 = fmaf(t3.x, vv.z, a10);
            a11 = fmaf(t3.y, vv.w, a11);
        }
        float acc0 = a00 + a01;
        float acc1 = a10 + a11;
#pragma unroll
        for (int o = 16; o; o >>= 1) {
            acc0 += __shfl_xor_sync(0xffffffffu, acc0, o);
            acc1 += __shfl_xor_sync(0xffffffffu, acc1, o);
        }
        if (lane == 0) {
            acc0 = msk0 ? acc0 : -1e30f;
            acc1 = msk1 ? acc1 : -1e30f;
            ga[(size_t)t * SS] = acc0;
            ga[(size_t)t * SS + 1] = acc1;
            scbuf[t][warp * 2] = acc0;
            scbuf[t][warp * 2 + 1] = acc1;
        }
    }
    __syncthreads();

    // per-slice stats: thread t handles row t over 32 local s
    if (tid < TT) {
        int t = tid;
        float m = -1e30f;
#pragma unroll
        for (int s = 0; s < 32; s++) m = fmaxf(m, scbuf[t][s]);
        float l = 0.f;
#pragma unroll
        for (int s = 0; s < 32; s++) l += __expf(scbuf[t][s] - m);
        g_pstat[b][scb][t] = make_float2(m, l);
    }
}

// ---------------------------------------------------------------------------
// K4: fused softmax-normalize + context (+ out_att from dc==0 blocks).
// grid (dc=8, sc=32, b=4) = 1024 blocks, 128 thr. Combines g_pstat slices
// into global (mx, 1/tot) per t, normalizes raw attn on the fly.
// ---------------------------------------------------------------------------
__global__ __launch_bounds__(128) void ctx_kernel(const float* __restrict__ states,
                                                  float* __restrict__ out_ctx,
                                                  float* __restrict__ out_att) {
    int dc = blockIdx.x, scb = blockIdx.y, b = blockIdx.z;
    int d = dc * 128 + threadIdx.x;
    int s0 = scb * 32;
    __shared__ float aw[TT][32];
    __shared__ float stat_m[TT], stat_i[TT];

    if (threadIdx.x < TT) {
        int t = threadIdx.x;
        float mx = -1e30f;
#pragma unroll
        for (int i = 0; i < 32; i++) mx = fmaxf(mx, g_pstat[b][i][t].x);
        float tot = 0.f;
#pragma unroll
        for (int i = 0; i < 32; i++) {
            float2 p = g_pstat[b][i][t];
            tot += p.y * __expf(p.x - mx);
        }
        stat_m[t] = mx;
        stat_i[t] = 1.0f / tot;
    }
    __syncthreads();

    for (int i = threadIdx.x; i < TT * 32; i += 128) {
        int t = i >> 5, sl = i & 31;
        float raw = g_attn[(size_t)(b * TT + t) * SS + s0 + sl];
        aw[t][sl] = __expf(raw - stat_m[t]) * stat_i[t];
    }
    __syncthreads();

    if (dc == 0) {
        float* oa = out_att + (size_t)b * SS * TT;
        for (int i = threadIdx.x; i < 32 * TT; i += 128) {
            int sl = i >> 5, t = i & 31;
            oa[(size_t)(s0 + sl) * TT + t] = aw[t][sl];
        }
    }

    float acc[TT] = {};
    const float* sb = states + ((size_t)b * SS + s0) * H2 + d;
#pragma unroll 4
    for (int sl = 0; sl < 32; sl++) {
        float sv = sb[(size_t)sl * H2];
#pragma unroll
        for (int t = 0; t < TT; t++) acc[t] = fmaf(aw[t][sl], sv, acc[t]);
    }
#pragma unroll
    for (int t = 0; t < TT; t++)
        atomicAdd(&out_ctx[(size_t)(b * TT + t) * H2 + d], acc[t]);
}

// ---------------------------------------------------------------------------
// K5: attention_hidden += context @ Wc[0:1024]. Split-K atomics.
// ---------------------------------------------------------------------------
__global__ __launch_bounds__(128) void hidden_kernel(const float* __restrict__ Wc,
                                                     const float* __restrict__ ctx,
                                                     float* __restrict__ out_hid) {
    int hc = blockIdx.x, tg = blockIdx.y;
    int b = blockIdx.z >> 4, kc = blockIdx.z & 15;
    int h = hc * 128 + threadIdx.x;
    int t0 = tg * 8, k0 = kc * 64;
    __shared__ float cc[8][64];
    for (int i = threadIdx.x; i < 8 * 64; i += 128) {
        int r = i >> 6, col = i & 63;
        cc[r][col] = ctx[(size_t)(b * TT + t0 + r) * H2 + k0 + col];
    }
    __syncthreads();
    float acc[8] = {};
#pragma unroll 4
    for (int k = 0; k < 64; k++) {
        float w = Wc[(size_t)(k0 + k) * HH + h];
#pragma unroll
        for (int i = 0; i < 8; i++) acc[i] = fmaf(cc[i][k], w, acc[i]);
    }
#pragma unroll
    for (int i = 0; i < 8; i++)
        atomicAdd(&out_hid[(size_t)(b * TT + t0 + i) * HH + h], acc[i]);
}

// ---------------------------------------------------------------------------
extern "C" void kernel_launch(void* const* d_in, const int* in_sizes, int n_in,
                              void* d_out, int out_size) {
    const float* query  = (const float*)d_in[0];
    const float* states = (const float*)d_in[1];
    const int*   mask   = (const int*)d_in[2];
    const float* Wq     = (const float*)d_in[3];
    const float* bq     = (const float*)d_in[4];
    const float* Ws     = (const float*)d_in[5];
    const float* v      = (const float*)d_in[6];
    const float* Wc     = (const float*)d_in[7];
    const float* bc     = (const float*)d_in[8];

    float* out_ctx = (float*)d_out;                  // (B,T,2H)
    float* out_hid = out_ctx + BB * TT * H2;         // (B,T,H)
    float* out_att = out_hid + BB * TT * HH;         // (B,S,T)

    static cudaStream_t s1 = nullptr, s2 = nullptr;
    static cudaEvent_t ef, e1, e2, e3;
    if (!s1) {
        cudaStreamCreateWithFlags(&s1, cudaStreamNonBlocking);
        cudaStreamCreateWithFlags(&s2, cudaStreamNonBlocking);
        cudaEventCreateWithFlags(&ef, cudaEventDisableTiming);
        cudaEventCreateWithFlags(&e1, cudaEventDisableTiming);
        cudaEventCreateWithFlags(&e2, cudaEventDisableTiming);
        cudaEventCreateWithFlags(&e3, cudaEventDisableTiming);
        cudaFuncSetAttribute(align_kernel,
                             cudaFuncAttributeMaxDynamicSharedMemorySize,
                             TT * H2 * sizeof(float));
        cudaFuncSetAttribute(sf_mma,
                             cudaFuncAttributeMaxDynamicSharedMemorySize,
                             SMEM_MMA);
    }

    // fork
    cudaEventRecord(ef, 0);
    cudaStreamWaitEvent(s1, ef, 0);
    cudaStreamWaitEvent(s2, ef, 0);

    prep_B<<<dim3(16, 16), 256, 0, s1>>>(Ws);
    cudaEventRecord(e1, s1);

    zero_kernel<<<48, 256, 0, s2>>>((float4*)out_ctx);  // ctx + hid
    qf_kernel<<<dim3(8, 4, 4), 128, 0, s2>>>(query, Wq, bq);
    cudaEventRecord(e2, s2);  // align only needs qf
    hid_q_kernel<<<dim3(4, 4, 32), 128, 0, s2>>>(query, Wc, bc, out_hid);
    cudaEventRecord(e3, s2);  // zero + hid_q done (gates ctx/hidden atomics)

    prep_A<<<1024, 256>>>(states);
    cudaStreamWaitEvent(0, e1, 0);  // prep_B done
    sf_mma<<<dim3(16, 16), 512, SMEM_MMA>>>();
    cudaStreamWaitEvent(0, e2, 0);  // qf done
    align_kernel<<<dim3(32, BB), 512, TT * H2 * sizeof(float)>>>(v, mask);
    cudaStreamWaitEvent(0, e3, 0);  // zero + hid_q done
    ctx_kernel<<<dim3(8, 32, 4), 128>>>(states, out_ctx, out_att);
    hidden_kernel<<<dim3(4, 4, 64), 128>>>(Wc, out_ctx, out_hid);
}

// round 14
// speedup vs baseline: 1.1740x; 1.0426x over previous
#include <cuda_runtime.h>
#include <cuda_fp16.h>
#include <cstdint>

#define BB 4
#define TT 32
#define SS 1024
#define HH 512
#define H2 1024
#define H3 1536

typedef unsigned long long ull;

// ---------------------------------------------------------------------------
// Scratch (allocation-free: __device__ globals)
// ---------------------------------------------------------------------------
__device__ float g_qf[BB * TT * H2];          // 512 KB
__device__ float g_sf[(size_t)BB * SS * H2];  // 16 MB
__device__ float g_attn[BB * TT * SS];        // 512 KB (masked raw scores)
__device__ float2 g_pstat[BB][32][TT];        // per-slice softmax stats (m, sumexp)
// fp16 operands, row-major K-major:
__device__ __align__(16) char gA_hi[8 << 20];  // states fp16 [4096][1024]
__device__ __align__(16) char gB_hi[2 << 20];  // Ws^T fp16 [1024][1024]

__device__ __forceinline__ uint32_t smem_u32(const void* p) {
    uint32_t a;
    asm("{ .reg .u64 t; cvta.to.shared.u64 t, %1; cvt.u32.u64 %0, t; }" : "=r"(a) : "l"(p));
    return a;
}

__device__ __forceinline__ uint32_t pack2h(float a, float b) {
    __half2 h = __floats2half2_rn(a, b);
    return *(uint32_t*)&h;
}

__device__ __forceinline__ uint32_t f16x2_pack(float lo, float hi) {
    uint32_t r;
    asm("cvt.rn.f16x2.f32 %0, %1, %2;" : "=r"(r) : "f"(hi), "f"(lo));
    return r;
}
__device__ __forceinline__ uint32_t tanh_h2(uint32_t x) {
    uint32_t y;
    asm("tanh.approx.f16x2 %0, %1;" : "=r"(y) : "r"(x));
    return y;
}
__device__ __forceinline__ float2 f16x2_unpack(uint32_t p) {
    float lo, hi;
    asm("{ .reg .b16 l, h; mov.b32 {l, h}, %2; cvt.f32.f16 %0, l; cvt.f32.f16 %1, h; }"
        : "=f"(lo), "=f"(hi) : "r"(p));
    return make_float2(lo, hi);
}

// ---- baseline-PTX tensor ops (sm_80+) -------------------------------------
#define LDSM_X4(r, a) \
    asm volatile("ldmatrix.sync.aligned.m8n8.x4.shared.b16 {%0,%1,%2,%3}, [%4];" \
                 : "=r"((r)[0]), "=r"((r)[1]), "=r"((r)[2]), "=r"((r)[3]) : "r"(a))

__device__ __forceinline__ void hmma(float* c, const uint32_t* a, uint32_t b0, uint32_t b1) {
    asm volatile(
        "mma.sync.aligned.m16n8k16.row.col.f32.f16.f16.f32 "
        "{%0,%1,%2,%3}, {%4,%5,%6,%7}, {%8,%9}, {%0,%1,%2,%3};"
        : "+f"(c[0]), "+f"(c[1]), "+f"(c[2]), "+f"(c[3])
        : "r"(a[0]), "r"(a[1]), "r"(a[2]), "r"(a[3]), "r"(b0), "r"(b1));
}

#define CP16(s, g) \
    asm volatile("cp.async.cg.shared.global [%0], [%1], 16;" :: "r"(s), "l"(g))
#define CPCOMMIT() asm volatile("cp.async.commit_group;" ::: "memory")
#define CPWAIT1() asm volatile("cp.async.wait_group 1;" ::: "memory")
#define CPWAIT0() asm volatile("cp.async.wait_group 0;" ::: "memory")

// ---------------------------------------------------------------------------
// K0: zero out_ctx + out_hid (atomicAdd targets). 196608 floats = 49152 f4.
// ---------------------------------------------------------------------------
__global__ __launch_bounds__(256) void zero_kernel(float4* __restrict__ p) {
    int i = blockIdx.x * 1024 + threadIdx.x;
#pragma unroll
    for (int u = 0; u < 4; u++) p[i + u * 256] = make_float4(0.f, 0.f, 0.f, 0.f);
}

// ---------------------------------------------------------------------------
// K1: qf = query @ Wq + bq   (128 x 1024, K=512)
// ---------------------------------------------------------------------------
__global__ __launch_bounds__(128) void qf_kernel(const float* __restrict__ query,
                                                 const float* __restrict__ Wq,
                                                 const float* __restrict__ bq) {
    int jc = blockIdx.x, tg = blockIdx.y, b = blockIdx.z;
    int j = jc * 128 + threadIdx.x;
    int t0 = tg * 8;
    __shared__ float q_s[8][HH];
    for (int i = threadIdx.x; i < 8 * HH; i += 128) {
        int r = i >> 9, c = i & (HH - 1);
        q_s[r][c] = query[(size_t)(b * TT + t0 + r) * HH + c];
    }
    __syncthreads();
    float acc[8];
    float bias = bq[j];
#pragma unroll
    for (int i = 0; i < 8; i++) acc[i] = bias;
#pragma unroll 8
    for (int k = 0; k < HH; k++) {
        float w = Wq[(size_t)k * H2 + j];
#pragma unroll
        for (int i = 0; i < 8; i++) acc[i] = fmaf(q_s[i][k], w, acc[i]);
    }
#pragma unroll
    for (int i = 0; i < 8; i++)
        g_qf[(size_t)(b * TT + t0 + i) * H2 + j] = acc[i];
}

// ---------------------------------------------------------------------------
// K1b: out_hid += query @ Wc[1024:1536] (+bc at kc==0). Split-K atomics.
// ---------------------------------------------------------------------------
__global__ __launch_bounds__(128) void hid_q_kernel(const float* __restrict__ query,
                                                    const float* __restrict__ Wc,
                                                    const float* __restrict__ bc,
                                                    float* __restrict__ out_hid) {
    int hc = blockIdx.x, tg = blockIdx.y;
    int b = blockIdx.z >> 3, kc = blockIdx.z & 7;
    int h = hc * 128 + threadIdx.x;
    int t0 = tg * 8, k0 = kc * 64;
    __shared__ float q_s[8][64];
    for (int i = threadIdx.x; i < 8 * 64; i += 128) {
        int r = i >> 6, c = i & 63;
        q_s[r][c] = query[(size_t)(b * TT + t0 + r) * HH + k0 + c];
    }
    __syncthreads();
    float acc[8];
    float bias = (kc == 0) ? bc[h] : 0.f;
#pragma unroll
    for (int i = 0; i < 8; i++) acc[i] = bias;
#pragma unroll 4
    for (int k = 0; k < 64; k++) {
        float w = Wc[(size_t)(H2 + k0 + k) * HH + h];
#pragma unroll
        for (int i = 0; i < 8; i++) acc[i] = fmaf(q_s[i][k], w, acc[i]);
    }
#pragma unroll
    for (int i = 0; i < 8; i++)
        atomicAdd(&out_hid[(size_t)(b * TT + t0 + i) * HH + h], acc[i]);
}

// ---------------------------------------------------------------------------
// prep_A: states fp32 [4096,1024] -> gA_hi fp16 row-major.
// ---------------------------------------------------------------------------
__global__ __launch_bounds__(256) void prep_A(const float* __restrict__ A) {
    int idx = blockIdx.x * 256 + threadIdx.x;
#pragma unroll
    for (int q = 0; q < 4; q++) {
        int fid = idx * 4 + q;
        float4 vvv = *(const float4*)(A + (size_t)fid * 4);
        ull hi = (ull)pack2h(vvv.x, vvv.y) | ((ull)pack2h(vvv.z, vvv.w) << 32);
        *(ull*)(gA_hi + (size_t)fid * 8) = hi;
    }
}

// ---------------------------------------------------------------------------
// prep_B: Ws fp32 [K=1024, N=1024] -> gB_hi fp16 transposed [N][K] (hi only).
// ---------------------------------------------------------------------------
__global__ __launch_bounds__(256) void prep_B(const float* __restrict__ W) {
    __shared__ float tr[64][65];
    int k0 = blockIdx.x * 64, n0 = blockIdx.y * 64;
    int tid = threadIdx.x;
    int ki = tid >> 2, nq = (tid & 3) * 16;
#pragma unroll
    for (int j = 0; j < 4; j++) {
        float4 vv = *(const float4*)(W + (size_t)(k0 + ki) * H2 + n0 + nq + j * 4);
        tr[nq + j * 4 + 0][ki] = vv.x;
        tr[nq + j * 4 + 1][ki] = vv.y;
        tr[nq + j * 4 + 2][ki] = vv.z;
        tr[nq + j * 4 + 3][ki] = vv.w;
    }
    __syncthreads();
    int nr_l = tid >> 2, kq = (tid & 3) * 16;
    int n_g = n0 + nr_l;
#pragma unroll
    for (int j = 0; j < 4; j++) {
        int kr = kq + j * 4;
        ull hi = (ull)pack2h(tr[nr_l][kr], tr[nr_l][kr + 1]) |
                 ((ull)pack2h(tr[nr_l][kr + 2], tr[nr_l][kr + 3]) << 32);
        *(ull*)(gB_hi + ((size_t)n_g * H2 + k0 + kr) * 2) = hi;
    }
}

// ---------------------------------------------------------------------------
// K2: sf = states @ Ws via mma.sync fp16 SINGLE MMA (Ah*Bh).
// Block tile 256x64, 512 thr, warp tile 64x16, grid 16x16 = 256 blocks.
// K-chunks 64, cp.async double buffer, 144B rows.
// ---------------------------------------------------------------------------
#define ROWB 144
#define A_TILE (256 * ROWB)     // 36864
#define B_TILE (64 * ROWB)      // 9216
#define STAGEB (A_TILE + B_TILE)  // 46080
#define SMEM_MMA (2 * STAGEB)     // 92160

__device__ __forceinline__ void load_chunk(uint32_t sst, const char* gAh,
                                           const char* gBh, int c, int tid) {
#pragma unroll
    for (int r = 0; r < 4; r++) {
        int i = r * 512 + tid;
        int row = i >> 3, quad = i & 7;
        uint32_t soff = row * ROWB + quad * 16;
        size_t goff = (size_t)row * 2048 + (size_t)c * 128 + quad * 16;
        CP16(sst + soff, gAh + goff);
    }
    {
        int row = tid >> 3, quad = tid & 7;
        uint32_t soff = row * ROWB + quad * 16;
        size_t goff = (size_t)row * 2048 + (size_t)c * 128 + quad * 16;
        CP16(sst + A_TILE + soff, gBh + goff);
    }
}

__global__ __launch_bounds__(512, 1) void sf_mma() {
    extern __shared__ __align__(16) char sm[];
    uint32_t sbase = smem_u32(sm);
    int tid = threadIdx.x, lane = tid & 31, warp = tid >> 5;
    int nt = blockIdx.x, mt = blockIdx.y;
    int wm = warp >> 2, wn = warp & 3;

    const char* gAh = gA_hi + (size_t)(mt * 256) * 2048;
    const char* gBh = gB_hi + (size_t)(nt * 64) * 2048;

    float cacc[4][2][4] = {};

    load_chunk(sbase, gAh, gBh, 0, tid);
    CPCOMMIT();

#pragma unroll 1
    for (int c = 0; c < 16; c++) {
        int cur = c & 1;
        if (c + 1 < 16) {
            load_chunk(sbase + (cur ^ 1) * STAGEB, gAh, gBh, c + 1, tid);
            CPCOMMIT();
            CPWAIT1();
        } else {
            CPWAIT0();
        }
        __syncthreads();

        uint32_t sA = sbase + cur * STAGEB;
        uint32_t sB = sA + A_TILE;
        int r16 = lane & 15, hx = lane >> 4;

#pragma unroll
        for (int k16 = 0; k16 < 4; k16++) {
            int kb = k16 * 32 + hx * 16;
            uint32_t ah[4][4];
#pragma unroll
            for (int mf = 0; mf < 4; mf++)
                LDSM_X4(ah[mf], sA + (wm * 64 + mf * 16 + r16) * ROWB + kb);
            uint32_t bh[4];
            LDSM_X4(bh, sB + (wn * 16 + r16) * ROWB + kb);
#pragma unroll
            for (int mf = 0; mf < 4; mf++)
#pragma unroll
                for (int nf = 0; nf < 2; nf++)
                    hmma(cacc[mf][nf], ah[mf], bh[nf], bh[nf + 2]);
        }
        __syncthreads();
    }

    int tg = lane >> 2, tq = lane & 3;
#pragma unroll
    for (int mf = 0; mf < 4; mf++) {
#pragma unroll
        for (int nf = 0; nf < 2; nf++) {
            float* base = g_sf + (size_t)(mt * 256 + wm * 64 + mf * 16 + tg) * H2 +
                          nt * 64 + wn * 16 + nf * 8 + tq * 2;
            float2 v0 = {cacc[mf][nf][0], cacc[mf][nf][1]};
            float2 v1 = {cacc[mf][nf][2], cacc[mf][nf][3]};
            *(float2*)base = v0;
            *(float2*)(base + 8 * H2) = v1;
        }
    }
}

// ---------------------------------------------------------------------------
// K3: alignments + mask + per-slice softmax stats.
// ---------------------------------------------------------------------------
__global__ __launch_bounds__(512, 1) void align_kernel(const float* __restrict__ v,
                                                       const int* __restrict__ mask) {
    extern __shared__ float qf_s[];       // [TT][H2] = 128 KB dynamic
    __shared__ float scbuf[TT][32];       // 4 KB static
    int scb = blockIdx.x, b = blockIdx.y;
    int tid = threadIdx.x, lane = tid & 31, warp = tid >> 5;

    const float4* qsrc = (const float4*)(g_qf + (size_t)b * TT * H2);
    float4* qdst = (float4*)qf_s;
#pragma unroll
    for (int i = 0; i < 16; i++) qdst[tid + i * 512] = qsrc[tid + i * 512];

    int s0 = scb * 32 + warp * 2;
    int msk0 = mask[b * SS + s0];
    int msk1 = mask[b * SS + s0 + 1];
    float4 sv[2][8];
#pragma unroll
    for (int si = 0; si < 2; si++) {
        const float* sfrow = g_sf + ((size_t)(b * SS + s0 + si)) * H2;
#pragma unroll
        for (int u = 0; u < 8; u++)
            sv[si][u] = *(const float4*)(sfrow + u * 128 + lane * 4);
    }
    __syncthreads();

    float* ga = g_attn + (size_t)(b * TT) * SS + s0;
#pragma unroll 1
    for (int t = 0; t < TT; t++) {
        const float* qrow = qf_s + t * H2;
        float a00 = 0.f, a01 = 0.f, a10 = 0.f, a11 = 0.f;
#pragma unroll
        for (int u = 0; u < 8; u++) {
            float4 q = *(const float4*)(qrow + u * 128 + lane * 4);
            float4 vv = __ldg((const float4*)(v + u * 128 + lane * 4));
            uint32_t p0 = tanh_h2(f16x2_pack(q.x + sv[0][u].x, q.y + sv[0][u].y));
            uint32_t p1 = tanh_h2(f16x2_pack(q.z + sv[0][u].z, q.w + sv[0][u].w));
            uint32_t p2 = tanh_h2(f16x2_pack(q.x + sv[1][u].x, q.y + sv[1][u].y));
            uint32_t p3 = tanh_h2(f16x2_pack(q.z + sv[1][u].z, q.w + sv[1][u].w));
            float2 t0 = f16x2_unpack(p0), t1 = f16x2_unpack(p1);
            float2 t2 = f16x2_unpack(p2), t3 = f16x2_unpack(p3);
            a00 = fmaf(t0.x, vv.x, a00);
            a01 = fmaf(t0.y, vv.y, a01);
            a00 = fmaf(t1.x, vv.z, a00);
            a01 = fmaf(t1.y, vv.w, a01);
            a10 = fmaf(t2.x, vv.x, a10);
            a11 = fmaf(t2.y, vv.y, a11);
            a10 = fmaf(t3.x, vv.z, a10);
            a11 = fmaf(t3.y, vv.w, a11);
        }
        float acc0 = a00 + a01;
        float acc1 = a10 + a11;
#pragma unroll
        for (int o = 16; o; o >>= 1) {
            acc0 += __shfl_xor_sync(0xffffffffu, acc0, o);
            acc1 += __shfl_xor_sync(0xffffffffu, acc1, o);
        }
        if (lane == 0) {
            acc0 = msk0 ? acc0 : -1e30f;
            acc1 = msk1 ? acc1 : -1e30f;
            ga[(size_t)t * SS] = acc0;
            ga[(size_t)t * SS + 1] = acc1;
            scbuf[t][warp * 2] = acc0;
            scbuf[t][warp * 2 + 1] = acc1;
        }
    }
    __syncthreads();

    if (tid < TT) {
        int t = tid;
        float m = -1e30f;
#pragma unroll
        for (int s = 0; s < 32; s++) m = fmaxf(m, scbuf[t][s]);
        float l = 0.f;
#pragma unroll
        for (int s = 0; s < 32; s++) l += __expf(scbuf[t][s] - m);
        g_pstat[b][scb][t] = make_float2(m, l);
    }
}

// ---------------------------------------------------------------------------
// K4: fused softmax-normalize + context (+ out_att from dc==0 blocks).
// ---------------------------------------------------------------------------
__global__ __launch_bounds__(128) void ctx_kernel(const float* __restrict__ states,
                                                  float* __restrict__ out_ctx,
                                                  float* __restrict__ out_att) {
    int dc = blockIdx.x, scb = blockIdx.y, b = blockIdx.z;
    int d = dc * 128 + threadIdx.x;
    int s0 = scb * 32;
    __shared__ float aw[TT][32];
    __shared__ float stat_m[TT], stat_i[TT];

    if (threadIdx.x < TT) {
        int t = threadIdx.x;
        float mx = -1e30f;
#pragma unroll
        for (int i = 0; i < 32; i++) mx = fmaxf(mx, g_pstat[b][i][t].x);
        float tot = 0.f;
#pragma unroll
        for (int i = 0; i < 32; i++) {
            float2 p = g_pstat[b][i][t];
            tot += p.y * __expf(p.x - mx);
        }
        stat_m[t] = mx;
        stat_i[t] = 1.0f / tot;
    }
    __syncthreads();

    for (int i = threadIdx.x; i < TT * 32; i += 128) {
        int t = i >> 5, sl = i & 31;
        float raw = g_attn[(size_t)(b * TT + t) * SS + s0 + sl];
        aw[t][sl] = __expf(raw - stat_m[t]) * stat_i[t];
    }
    __syncthreads();

    if (dc == 0) {
        float* oa = out_att + (size_t)b * SS * TT;
        for (int i = threadIdx.x; i < 32 * TT; i += 128) {
            int sl = i >> 5, t = i & 31;
            oa[(size_t)(s0 + sl) * TT + t] = aw[t][sl];
        }
    }

    float acc[TT] = {};
    const float* sb = states + ((size_t)b * SS + s0) * H2 + d;
#pragma unroll 4
    for (int sl = 0; sl < 32; sl++) {
        float sv = sb[(size_t)sl * H2];
#pragma unroll
        for (int t = 0; t < TT; t++) acc[t] = fmaf(aw[t][sl], sv, acc[t]);
    }
#pragma unroll
    for (int t = 0; t < TT; t++)
        atomicAdd(&out_ctx[(size_t)(b * TT + t) * H2 + d], acc[t]);
}

// ---------------------------------------------------------------------------
// K5: attention_hidden += context @ Wc[0:1024]. Split-K atomics.
// ---------------------------------------------------------------------------
__global__ __launch_bounds__(128) void hidden_kernel(const float* __restrict__ Wc,
                                                     const float* __restrict__ ctx,
                                                     float* __restrict__ out_hid) {
    int hc = blockIdx.x, tg = blockIdx.y;
    int b = blockIdx.z >> 4, kc = blockIdx.z & 15;
    int h = hc * 128 + threadIdx.x;
    int t0 = tg * 8, k0 = kc * 64;
    __shared__ float cc[8][64];
    for (int i = threadIdx.x; i < 8 * 64; i += 128) {
        int r = i >> 6, col = i & 63;
        cc[r][col] = ctx[(size_t)(b * TT + t0 + r) * H2 + k0 + col];
    }
    __syncthreads();
    float acc[8] = {};
#pragma unroll 4
    for (int k = 0; k < 64; k++) {
        float w = Wc[(size_t)(k0 + k) * HH + h];
#pragma unroll
        for (int i = 0; i < 8; i++) acc[i] = fmaf(cc[i][k], w, acc[i]);
    }
#pragma unroll
    for (int i = 0; i < 8; i++)
        atomicAdd(&out_hid[(size_t)(b * TT + t0 + i) * HH + h], acc[i]);
}

// ---------------------------------------------------------------------------
extern "C" void kernel_launch(void* const* d_in, const int* in_sizes, int n_in,
                              void* d_out, int out_size) {
    const float* query  = (const float*)d_in[0];
    const float* states = (const float*)d_in[1];
    const int*   mask   = (const int*)d_in[2];
    const float* Wq     = (const float*)d_in[3];
    const float* bq     = (const float*)d_in[4];
    const float* Ws     = (const float*)d_in[5];
    const float* v      = (const float*)d_in[6];
    const float* Wc     = (const float*)d_in[7];
    const float* bc     = (const float*)d_in[8];

    float* out_ctx = (float*)d_out;                  // (B,T,2H)
    float* out_hid = out_ctx + BB * TT * H2;         // (B,T,H)
    float* out_att = out_hid + BB * TT * HH;         // (B,S,T)

    static cudaStream_t s1 = nullptr, s2 = nullptr;
    static cudaEvent_t ef, e1, e2, e3;
    if (!s1) {
        cudaStreamCreateWithFlags(&s1, cudaStreamNonBlocking);
        cudaStreamCreateWithFlags(&s2, cudaStreamNonBlocking);
        cudaEventCreateWithFlags(&ef, cudaEventDisableTiming);
        cudaEventCreateWithFlags(&e1, cudaEventDisableTiming);
        cudaEventCreateWithFlags(&e2, cudaEventDisableTiming);
        cudaEventCreateWithFlags(&e3, cudaEventDisableTiming);
        cudaFuncSetAttribute(align_kernel,
                             cudaFuncAttributeMaxDynamicSharedMemorySize,
                             TT * H2 * sizeof(float));
        cudaFuncSetAttribute(sf_mma,
                             cudaFuncAttributeMaxDynamicSharedMemorySize,
                             SMEM_MMA);
    }

    // fork
    cudaEventRecord(ef, 0);
    cudaStreamWaitEvent(s1, ef, 0);
    cudaStreamWaitEvent(s2, ef, 0);

    prep_B<<<dim3(16, 16), 256, 0, s1>>>(Ws);
    cudaEventRecord(e1, s1);

    zero_kernel<<<48, 256, 0, s2>>>((float4*)out_ctx);  // ctx + hid
    qf_kernel<<<dim3(8, 4, 4), 128, 0, s2>>>(query, Wq, bq);
    cudaEventRecord(e2, s2);  // align only needs qf
    hid_q_kernel<<<dim3(4, 4, 32), 128, 0, s2>>>(query, Wc, bc, out_hid);
    cudaEventRecord(e3, s2);  // zero + hid_q done (gates ctx/hidden atomics)

    prep_A<<<1024, 256>>>(states);
    cudaStreamWaitEvent(0, e1, 0);  // prep_B done
    sf_mma<<<dim3(16, 16), 512, SMEM_MMA>>>();
    cudaStreamWaitEvent(0, e2, 0);  // qf done
    align_kernel<<<dim3(32, BB), 512, TT * H2 * sizeof(float)>>>(v, mask);
    cudaStreamWaitEvent(0, e3, 0);  // zero + hid_q done
    ctx_kernel<<<dim3(8, 32, 4), 128>>>(states, out_ctx, out_att);
    hidden_kernel<<<dim3(4, 4, 64), 128>>>(Wc, out_ctx, out_hid);
}